// round 14
// baseline (speedup 1.0000x reference)
#include <cuda_runtime.h>
#include <cuda_fp16.h>
#include <cstdint>

// ---------------------------------------------------------------------------
// Device scratch: featuremap as fp16, x-pair duplicated. Entry (y,x) is 16B:
//   [ c0..c3 @(y,x) , c0..c3 @(y,min(x+1,511)) ]  as 8 halves.
// One LDG.128 fetches BOTH x-taps of one row -> 2 loads per bilinear sample.
// ---------------------------------------------------------------------------
__device__ uint4 g_fmH[512 * 512];

__global__ void fm_pack_kernel(const float* __restrict__ fm) {
    int i = blockIdx.x * blockDim.x + threadIdx.x;
    if (i >= 512 * 512) return;
    int x  = i & 511;
    int xn = min(x + 1, 511);
    int j  = i - x + xn;

    __half2 p01 = __floats2half2_rn(fm[i],              fm[i + 262144]);
    __half2 p23 = __floats2half2_rn(fm[i + 2 * 262144], fm[i + 3 * 262144]);
    __half2 q01 = __floats2half2_rn(fm[j],              fm[j + 262144]);
    __half2 q23 = __floats2half2_rn(fm[j + 2 * 262144], fm[j + 3 * 262144]);

    uint4 e;
    e.x = *reinterpret_cast<unsigned*>(&p01);
    e.y = *reinterpret_cast<unsigned*>(&p23);
    e.z = *reinterpret_cast<unsigned*>(&q01);
    e.w = *reinterpret_cast<unsigned*>(&q23);
    g_fmH[i] = e;
}

// ---------------------------------------------------------------------------
// helpers
// ---------------------------------------------------------------------------
__device__ __forceinline__ unsigned h2u(float a, float b) {
    __half2 h = __floats2half2_rn(a, b);
    return *reinterpret_cast<unsigned*>(&h);
}
__device__ __forceinline__ unsigned relu_pack(float a, float b) {
    __half2 h = __floats2half2_rn(a, b);
    h = __hmax2(h, __floats2half2_rn(0.0f, 0.0f));
    return *reinterpret_cast<unsigned*>(&h);
}
__device__ __forceinline__ __half2 u2h(unsigned u) {
    return *reinterpret_cast<__half2*>(&u);
}

// m16n8k16 fp16 -> fp32
__device__ __forceinline__ void mma_16816(float d[4], const unsigned a[4],
                                          const unsigned b[2], const float c[4]) {
    asm volatile(
        "mma.sync.aligned.m16n8k16.row.col.f32.f16.f16.f32 "
        "{%0,%1,%2,%3}, {%4,%5,%6,%7}, {%8,%9}, {%10,%11,%12,%13};\n"
        : "=f"(d[0]), "=f"(d[1]), "=f"(d[2]), "=f"(d[3])
        : "r"(a[0]), "r"(a[1]), "r"(a[2]), "r"(a[3]),
          "r"(b[0]), "r"(b[1]),
          "f"(c[0]), "f"(c[1]), "f"(c[2]), "f"(c[3]));
}
// m16n8k8 fp16 -> fp32
__device__ __forceinline__ void mma_1688(float d[4], const unsigned a[2],
                                         unsigned b, const float c[4]) {
    asm volatile(
        "mma.sync.aligned.m16n8k8.row.col.f32.f16.f16.f32 "
        "{%0,%1,%2,%3}, {%4,%5}, {%6}, {%7,%8,%9,%10};\n"
        : "=f"(d[0]), "=f"(d[1]), "=f"(d[2]), "=f"(d[3])
        : "r"(a[0]), "r"(a[1]), "r"(b),
          "f"(c[0]), "f"(c[1]), "f"(c[2]), "f"(c[3]));
}

// issue gather loads for one point; results + packed (wx,wy) carried in regs.
// address via exact fp32 fma: y0f*512 + x0f < 2^18, exact.
__device__ __forceinline__ void issue_gather(float u, float v,
                                             uint4& r0, uint4& r1,
                                             unsigned& wxy) {
    float fx = fminf(fmaxf(fmaf(u, 512.0f, -0.5f), 0.0f), 511.0f);
    float fy = fminf(fmaxf(fmaf(v, 512.0f, -0.5f), 0.0f), 511.0f);
    float x0f = floorf(fx), y0f = floorf(fy);
    wxy = h2u(fx - x0f, fy - y0f);
    int idx0 = (int)fmaf(y0f, 512.0f, x0f);
    int idx1 = (int)fmaf(fminf(y0f + 1.0f, 511.0f), 512.0f, x0f);
    r0 = __ldg(&g_fmH[idx0]);
    r1 = __ldg(&g_fmH[idx1]);
}

// fp16 bilinear lerp on gathered rows -> two half2 (f0,f1),(f2,f3)
__device__ __forceinline__ void lerp_fm(const uint4& r0, const uint4& r1,
                                        unsigned wxy,
                                        unsigned& f01u, unsigned& f23u) {
    __half2 wxyh = u2h(wxy);
    __half2 wx2  = __low2half2(wxyh);
    __half2 wy2  = __high2half2(wxyh);

    __half2 A01 = u2h(r0.x), A23 = u2h(r0.y);
    __half2 B01 = u2h(r0.z), B23 = u2h(r0.w);
    __half2 C01 = u2h(r1.x), C23 = u2h(r1.y);
    __half2 D01 = u2h(r1.z), D23 = u2h(r1.w);

    __half2 t01 = __hfma2(wx2, __hsub2(B01, A01), A01);
    __half2 t23 = __hfma2(wx2, __hsub2(B23, A23), A23);
    __half2 s01 = __hfma2(wx2, __hsub2(D01, C01), C01);
    __half2 s23 = __hfma2(wx2, __hsub2(D23, C23), C23);
    __half2 f01 = __hfma2(wy2, __hsub2(s01, t01), t01);
    __half2 f23 = __hfma2(wy2, __hsub2(s23, t23), t23);
    f01u = *reinterpret_cast<unsigned*>(&f01);
    f23u = *reinterpret_cast<unsigned*>(&f23);
}

// ---------------------------------------------------------------------------
// Main kernel: 4 warps/block; each warp does 4 iterations x 64 points = 256.
// 4 m16 tiles per iteration -> 8 independent HMMA per layer (2 chains of ILP).
// Coords prefetched 2 iters ahead, gathers 1 iter ahead. sIn double-buffered.
// ---------------------------------------------------------------------------
__global__ __launch_bounds__(128, 4) void mlp_mma_kernel(
    const float* __restrict__ x,
    const float* __restrict__ W1, const float* __restrict__ b1,
    const float* __restrict__ W2, const float* __restrict__ b2,
    const float* __restrict__ W3, const float* __restrict__ b3,
    const float* __restrict__ W4, const float* __restrict__ b4,
    const float* __restrict__ W5, const float* __restrict__ b5,
    float* __restrict__ out, int n)
{
    __shared__ uint4 sIn[2][4][64];    // [buf][warp][row], 8 KB
    __shared__ float sOut[4][192];     // 64 pts x 3 per warp, 3 KB

    const int tid  = threadIdx.x;
    const int w    = tid >> 5;
    const int lane = tid & 31;
    const int g    = lane >> 2;       // 0..7
    const int q    = lane & 3;        // 0..3
    const int k0   = 2 * q;
    const int k1   = 2 * q + 1;

    // ---- per-thread weight/bias fragments (loaded once) ----
    // input row layout: [x, y, z, 0, f0, f1, f2, f3]  (pad at k=3)
    unsigned B1f[2];        float C1f[2][2];
    unsigned B2f[2][2];     float C2f[2][2];
    unsigned B3f[2][2];     float C3f[2][2];
    unsigned B4f[2][2];     float C4f[2][2];
    unsigned B5f[2];        float C5f[2];

#pragma unroll
    for (int t = 0; t < 2; t++) {
        int nn = 8 * t + g;
        float w0 = (k0 < 3) ? __ldg(&W1[k0 * 16 + nn])
                            : ((k0 == 3) ? 0.0f : __ldg(&W1[(k0 - 1) * 16 + nn]));
        float w1 = (k1 < 3) ? __ldg(&W1[k1 * 16 + nn])
                            : ((k1 == 3) ? 0.0f : __ldg(&W1[(k1 - 1) * 16 + nn]));
        B1f[t] = h2u(w0, w1);
        C1f[t][0] = __ldg(&b1[8 * t + k0]);
        C1f[t][1] = __ldg(&b1[8 * t + k1]);

        B2f[t][0] = h2u(__ldg(&W2[k0 * 16 + nn]),       __ldg(&W2[k1 * 16 + nn]));
        B2f[t][1] = h2u(__ldg(&W2[(k0 + 8) * 16 + nn]), __ldg(&W2[(k1 + 8) * 16 + nn]));
        C2f[t][0] = __ldg(&b2[8 * t + k0]);
        C2f[t][1] = __ldg(&b2[8 * t + k1]);

        B3f[t][0] = h2u(__ldg(&W3[k0 * 16 + nn]),       __ldg(&W3[k1 * 16 + nn]));
        B3f[t][1] = h2u(__ldg(&W3[(k0 + 8) * 16 + nn]), __ldg(&W3[(k1 + 8) * 16 + nn]));
        C3f[t][0] = __ldg(&b3[8 * t + k0]);
        C3f[t][1] = __ldg(&b3[8 * t + k1]);

        B4f[t][0] = h2u(__ldg(&W4[k0 * 16 + nn]),       __ldg(&W4[k1 * 16 + nn]));
        B4f[t][1] = h2u(__ldg(&W4[(k0 + 8) * 16 + nn]), __ldg(&W4[(k1 + 8) * 16 + nn]));
        C4f[t][0] = __ldg(&b4[8 * t + k0]);
        C4f[t][1] = __ldg(&b4[8 * t + k1]);
    }
    {
        float w50 = (g < 3) ? __ldg(&W5[k0 * 3 + g]) : 0.0f;
        float w51 = (g < 3) ? __ldg(&W5[k1 * 3 + g]) : 0.0f;
        float w52 = (g < 3) ? __ldg(&W5[(k0 + 8) * 3 + g]) : 0.0f;
        float w53 = (g < 3) ? __ldg(&W5[(k1 + 8) * 3 + g]) : 0.0f;
        B5f[0] = h2u(w50, w51);
        B5f[1] = h2u(w52, w53);
        C5f[0] = (k0 < 3) ? __ldg(&b5[k0]) : 0.0f;
        C5f[1] = (k1 < 3) ? __ldg(&b5[k1]) : 0.0f;
    }

    const long warpbase = (long)blockIdx.x * 1024 + w * 256;
    if (warpbase >= n) return;

    // ---- prefetch state (two halves of the 64-pt batch) ----
    float cu[2], cv[2], cz[2];
    float nu[2], nv[2], nz[2];
    uint4 cr0[2], cr1[2];
    unsigned cwxy[2];

    auto load_coords = [&](int it, int h, float& a, float& b, float& c) {
        long p = warpbase + (long)it * 64 + h * 32 + lane;
        if (it < 4 && p < (long)n) {
            a = __ldg(&x[p * 3 + 0]);
            b = __ldg(&x[p * 3 + 1]);
            c = __ldg(&x[p * 3 + 2]);
        } else {
            a = 0.0f; b = 0.0f; c = 0.0f;
        }
    };

    // prologue
#pragma unroll
    for (int h = 0; h < 2; h++) {
        load_coords(0, h, cu[h], cv[h], cz[h]);
        issue_gather(cu[h], cv[h], cr0[h], cr1[h], cwxy[h]);
        load_coords(1, h, nu[h], nv[h], nz[h]);
    }

    for (int it = 0; it < 4; it++) {
        long pbase = warpbase + (long)it * 64;
        if (pbase >= n) break;                 // warp-uniform
        const int buf = it & 1;

        // ---- lerp + stage input rows for both halves ----
#pragma unroll
        for (int h = 0; h < 2; h++) {
            unsigned f01u, f23u;
            lerp_fm(cr0[h], cr1[h], cwxy[h], f01u, f23u);
            uint4 row;
            row.x = h2u(cu[h], cv[h]);
            row.y = h2u(cz[h], 0.0f);
            row.z = f01u;
            row.w = f23u;
            sIn[buf][w][h * 32 + lane] = row;
        }
        __syncwarp();

        // ---- ldmatrix x4 twice: 8 k8-fragments = 4 m16 tiles ----
        unsigned a[8];
        {
            unsigned addr0 = (unsigned)__cvta_generic_to_shared(&sIn[buf][w][lane]);
            asm volatile(
                "ldmatrix.sync.aligned.m8n8.x4.shared.b16 {%0,%1,%2,%3}, [%4];\n"
                : "=r"(a[0]), "=r"(a[1]), "=r"(a[2]), "=r"(a[3]) : "r"(addr0));
            unsigned addr1 = (unsigned)__cvta_generic_to_shared(&sIn[buf][w][32 + lane]);
            asm volatile(
                "ldmatrix.sync.aligned.m8n8.x4.shared.b16 {%0,%1,%2,%3}, [%4];\n"
                : "=r"(a[4]), "=r"(a[5]), "=r"(a[6]), "=r"(a[7]) : "r"(addr1));
        }

        // ---- prefetch: gathers for it+1, coords for it+2 ----
#pragma unroll
        for (int h = 0; h < 2; h++) {
            issue_gather(nu[h], nv[h], cr0[h], cr1[h], cwxy[h]);
            cu[h] = nu[h]; cv[h] = nv[h]; cz[h] = nz[h];
            load_coords(it + 2, h, nu[h], nv[h], nz[h]);
        }

        // ---- layer 1 (k=8) on 4 tiles ----
        unsigned A[4][4];
#pragma unroll
        for (int T = 0; T < 4; T++) {
            unsigned A1[2] = {a[2 * T], a[2 * T + 1]};
            float c0[4] = {C1f[0][0], C1f[0][1], C1f[0][0], C1f[0][1]};
            float c1[4] = {C1f[1][0], C1f[1][1], C1f[1][0], C1f[1][1]};
            float d0[4], d1[4];
            mma_1688(d0, A1, B1f[0], c0);
            mma_1688(d1, A1, B1f[1], c1);
            A[T][0] = relu_pack(d0[0], d0[1]);
            A[T][1] = relu_pack(d0[2], d0[3]);
            A[T][2] = relu_pack(d1[0], d1[1]);
            A[T][3] = relu_pack(d1[2], d1[3]);
        }

        // ---- layers 2-4 on 4 tiles ----
        const unsigned (*Bs[3])[2] = {B2f, B3f, B4f};
        const float    (*Cs[3])[2] = {C2f, C3f, C4f};
#pragma unroll
        for (int L = 0; L < 3; L++) {
#pragma unroll
            for (int T = 0; T < 4; T++) {
                float c0[4] = {Cs[L][0][0], Cs[L][0][1], Cs[L][0][0], Cs[L][0][1]};
                float c1[4] = {Cs[L][1][0], Cs[L][1][1], Cs[L][1][0], Cs[L][1][1]};
                float d0[4], d1[4];
                mma_16816(d0, A[T], Bs[L][0], c0);
                mma_16816(d1, A[T], Bs[L][1], c1);
                A[T][0] = relu_pack(d0[0], d0[1]);
                A[T][1] = relu_pack(d0[2], d0[3]);
                A[T][2] = relu_pack(d1[0], d1[1]);
                A[T][3] = relu_pack(d1[2], d1[3]);
            }
        }

        // ---- layer 5 (n=3 padded to 8) ----
        float d5[4][4];
#pragma unroll
        for (int T = 0; T < 4; T++) {
            float c[4] = {C5f[0], C5f[1], C5f[0], C5f[1]};
            mma_16816(d5[T], A[T], B5f, c);
        }

        // ---- stage outputs: tile T covers points pbase + T*16 + row ----
        if (q == 0) {
#pragma unroll
            for (int T = 0; T < 4; T++) {
                sOut[w][(T * 16 + g) * 3 + 0]     = d5[T][0];
                sOut[w][(T * 16 + g) * 3 + 1]     = d5[T][1];
                sOut[w][(T * 16 + g + 8) * 3 + 0] = d5[T][2];
                sOut[w][(T * 16 + g + 8) * 3 + 1] = d5[T][3];
            }
        } else if (q == 1) {
#pragma unroll
            for (int T = 0; T < 4; T++) {
                sOut[w][(T * 16 + g) * 3 + 2]     = d5[T][0];
                sOut[w][(T * 16 + g + 8) * 3 + 2] = d5[T][2];
            }
        }
        __syncwarp();

        // ---- store 192 contiguous floats (48 float4) ----
        if (pbase + 64 <= (long)n) {
            float4* dst = reinterpret_cast<float4*>(out + pbase * 3);
            const float4* src = reinterpret_cast<const float4*>(sOut[w]);
            dst[lane] = src[lane];
            if (lane < 16) dst[32 + lane] = src[32 + lane];
        } else {
            int cnt = (int)(n - pbase) * 3;
            for (int idx = lane; idx < cnt; idx += 32)
                out[pbase * 3 + idx] = sOut[w][idx];
        }
        __syncwarp();
    }
}

// ---------------------------------------------------------------------------
// kernel_launch — graph-capturable, allocation-free.
// ---------------------------------------------------------------------------
extern "C" void kernel_launch(void* const* d_in, const int* in_sizes, int n_in,
                              void* d_out, int out_size) {
    const float* x  = (const float*)d_in[0];
    const float* fm = (const float*)d_in[1];
    const float* W1 = (const float*)d_in[2];
    const float* b1 = (const float*)d_in[3];
    const float* W2 = (const float*)d_in[4];
    const float* b2 = (const float*)d_in[5];
    const float* W3 = (const float*)d_in[6];
    const float* b3 = (const float*)d_in[7];
    const float* W4 = (const float*)d_in[8];
    const float* b4 = (const float*)d_in[9];
    const float* W5 = (const float*)d_in[10];
    const float* b5 = (const float*)d_in[11];

    int n = in_sizes[0] / 3;   // 4,000,000 points

    fm_pack_kernel<<<(512 * 512 + 255) / 256, 256>>>(fm);

    int nblocks = (n + 1023) / 1024;   // 1024 points per block
    mlp_mma_kernel<<<nblocks, 128>>>(x, W1, b1, W2, b2, W3, b3, W4, b4, W5, b5,
                                     (float*)d_out, n);
}

// round 15
// speedup vs baseline: 1.0969x; 1.0969x over previous
#include <cuda_runtime.h>
#include <cuda_fp16.h>
#include <cstdint>

// ---------------------------------------------------------------------------
// Device scratch: featuremap as fp16, x-pair duplicated. Entry (y,x) is 16B:
//   [ c0..c3 @(y,x) , c0..c3 @(y,min(x+1,511)) ]  as 8 halves.
// One LDG.128 fetches BOTH x-taps of one row -> 2 loads per bilinear sample.
// ---------------------------------------------------------------------------
__device__ uint4 g_fmH[512 * 512];

__global__ void fm_pack_kernel(const float* __restrict__ fm) {
    int i = blockIdx.x * blockDim.x + threadIdx.x;
    if (i >= 512 * 512) return;
    int x  = i & 511;
    int xn = min(x + 1, 511);
    int j  = i - x + xn;

    __half2 p01 = __floats2half2_rn(fm[i],              fm[i + 262144]);
    __half2 p23 = __floats2half2_rn(fm[i + 2 * 262144], fm[i + 3 * 262144]);
    __half2 q01 = __floats2half2_rn(fm[j],              fm[j + 262144]);
    __half2 q23 = __floats2half2_rn(fm[j + 2 * 262144], fm[j + 3 * 262144]);

    uint4 e;
    e.x = *reinterpret_cast<unsigned*>(&p01);
    e.y = *reinterpret_cast<unsigned*>(&p23);
    e.z = *reinterpret_cast<unsigned*>(&q01);
    e.w = *reinterpret_cast<unsigned*>(&q23);
    g_fmH[i] = e;
}

// ---------------------------------------------------------------------------
// helpers
// ---------------------------------------------------------------------------
__device__ __forceinline__ unsigned h2u(float a, float b) {
    __half2 h = __floats2half2_rn(a, b);
    return *reinterpret_cast<unsigned*>(&h);
}
__device__ __forceinline__ unsigned relu_pack(float a, float b) {
    __half2 h = __floats2half2_rn(a, b);
    h = __hmax2(h, __floats2half2_rn(0.0f, 0.0f));
    return *reinterpret_cast<unsigned*>(&h);
}
__device__ __forceinline__ __half2 u2h(unsigned u) {
    return *reinterpret_cast<__half2*>(&u);
}

// m16n8k16 fp16 -> fp32
__device__ __forceinline__ void mma_16816(float d[4], const unsigned a[4],
                                          const unsigned b[2], const float c[4]) {
    asm volatile(
        "mma.sync.aligned.m16n8k16.row.col.f32.f16.f16.f32 "
        "{%0,%1,%2,%3}, {%4,%5,%6,%7}, {%8,%9}, {%10,%11,%12,%13};\n"
        : "=f"(d[0]), "=f"(d[1]), "=f"(d[2]), "=f"(d[3])
        : "r"(a[0]), "r"(a[1]), "r"(a[2]), "r"(a[3]),
          "r"(b[0]), "r"(b[1]),
          "f"(c[0]), "f"(c[1]), "f"(c[2]), "f"(c[3]));
}
// m16n8k8 fp16 -> fp32
__device__ __forceinline__ void mma_1688(float d[4], const unsigned a[2],
                                         unsigned b, const float c[4]) {
    asm volatile(
        "mma.sync.aligned.m16n8k8.row.col.f32.f16.f16.f32 "
        "{%0,%1,%2,%3}, {%4,%5}, {%6}, {%7,%8,%9,%10};\n"
        : "=f"(d[0]), "=f"(d[1]), "=f"(d[2]), "=f"(d[3])
        : "r"(a[0]), "r"(a[1]), "r"(b),
          "f"(c[0]), "f"(c[1]), "f"(c[2]), "f"(c[3]));
}

// hidden 16->16 layer on two m16 tiles; biases arrive packed as half2.
__device__ __forceinline__ void hidden16(unsigned A[2][4],
                                         const unsigned B[2][2],
                                         const unsigned Cp[2]) {
    float2 cb0 = __half22float2(u2h(Cp[0]));
    float2 cb1 = __half22float2(u2h(Cp[1]));
#pragma unroll
    for (int T = 0; T < 2; T++) {
        float c0[4] = {cb0.x, cb0.y, cb0.x, cb0.y};
        float c1[4] = {cb1.x, cb1.y, cb1.x, cb1.y};
        float d0[4], d1[4];
        mma_16816(d0, A[T], B[0], c0);
        mma_16816(d1, A[T], B[1], c1);
        A[T][0] = relu_pack(d0[0], d0[1]);
        A[T][1] = relu_pack(d0[2], d0[3]);
        A[T][2] = relu_pack(d1[0], d1[1]);
        A[T][3] = relu_pack(d1[2], d1[3]);
    }
}

// issue gather loads for one point; results + packed (wx,wy) carried in regs.
// address via exact fp32 fma: y0f*512 + x0f < 2^18, exact.
__device__ __forceinline__ void issue_gather(float u, float v,
                                             uint4& r0, uint4& r1,
                                             unsigned& wxy) {
    float fx = fminf(fmaxf(fmaf(u, 512.0f, -0.5f), 0.0f), 511.0f);
    float fy = fminf(fmaxf(fmaf(v, 512.0f, -0.5f), 0.0f), 511.0f);
    float x0f = floorf(fx), y0f = floorf(fy);
    wxy = h2u(fx - x0f, fy - y0f);
    int idx0 = (int)fmaf(y0f, 512.0f, x0f);
    int idx1 = (int)fmaf(fminf(y0f + 1.0f, 511.0f), 512.0f, x0f);
    r0 = __ldg(&g_fmH[idx0]);
    r1 = __ldg(&g_fmH[idx1]);
}

// ---------------------------------------------------------------------------
// Main kernel: 4 warps/block, each warp 8 iterations x 32 points = 256 pts.
// Coords prefetched 2 iterations ahead, gathers 1 iteration ahead.
// Register-trimmed for 6 blocks/SM (24 warps).
// ---------------------------------------------------------------------------
__global__ __launch_bounds__(128, 6) void mlp_mma_kernel(
    const float* __restrict__ x,
    const float* __restrict__ W1, const float* __restrict__ b1,
    const float* __restrict__ W2, const float* __restrict__ b2,
    const float* __restrict__ W3, const float* __restrict__ b3,
    const float* __restrict__ W4, const float* __restrict__ b4,
    const float* __restrict__ W5, const float* __restrict__ b5,
    float* __restrict__ out, int n)
{
    __shared__ uint4 sIn[4][32];      // per-warp input rows (8 halves each)
    __shared__ float sOut[4][96];     // per-warp output staging (32 pts x 3)

    const int tid  = threadIdx.x;
    const int w    = tid >> 5;
    const int lane = tid & 31;
    const int g    = lane >> 2;       // 0..7
    const int q    = lane & 3;        // 0..3
    const int k0   = 2 * q;
    const int k1   = 2 * q + 1;

    // ---- per-thread weight/bias fragments (loaded once) ----
    // input row layout: [x, y, z, 0, f0, f1, f2, f3]  (pad at k=3)
    unsigned B1f[2];        unsigned C1p[2];
    unsigned B2f[2][2];     unsigned C2p[2];
    unsigned B3f[2][2];     unsigned C3p[2];
    unsigned B4f[2][2];     unsigned C4p[2];
    unsigned B5f[2];        unsigned C5p;

#pragma unroll
    for (int t = 0; t < 2; t++) {
        int nn = 8 * t + g;
        float w0 = (k0 < 3) ? __ldg(&W1[k0 * 16 + nn])
                            : ((k0 == 3) ? 0.0f : __ldg(&W1[(k0 - 1) * 16 + nn]));
        float w1 = (k1 < 3) ? __ldg(&W1[k1 * 16 + nn])
                            : ((k1 == 3) ? 0.0f : __ldg(&W1[(k1 - 1) * 16 + nn]));
        B1f[t] = h2u(w0, w1);
        C1p[t] = h2u(__ldg(&b1[8 * t + k0]), __ldg(&b1[8 * t + k1]));

        B2f[t][0] = h2u(__ldg(&W2[k0 * 16 + nn]),       __ldg(&W2[k1 * 16 + nn]));
        B2f[t][1] = h2u(__ldg(&W2[(k0 + 8) * 16 + nn]), __ldg(&W2[(k1 + 8) * 16 + nn]));
        C2p[t] = h2u(__ldg(&b2[8 * t + k0]), __ldg(&b2[8 * t + k1]));

        B3f[t][0] = h2u(__ldg(&W3[k0 * 16 + nn]),       __ldg(&W3[k1 * 16 + nn]));
        B3f[t][1] = h2u(__ldg(&W3[(k0 + 8) * 16 + nn]), __ldg(&W3[(k1 + 8) * 16 + nn]));
        C3p[t] = h2u(__ldg(&b3[8 * t + k0]), __ldg(&b3[8 * t + k1]));

        B4f[t][0] = h2u(__ldg(&W4[k0 * 16 + nn]),       __ldg(&W4[k1 * 16 + nn]));
        B4f[t][1] = h2u(__ldg(&W4[(k0 + 8) * 16 + nn]), __ldg(&W4[(k1 + 8) * 16 + nn]));
        C4p[t] = h2u(__ldg(&b4[8 * t + k0]), __ldg(&b4[8 * t + k1]));
    }
    {
        float w50 = (g < 3) ? __ldg(&W5[k0 * 3 + g]) : 0.0f;
        float w51 = (g < 3) ? __ldg(&W5[k1 * 3 + g]) : 0.0f;
        float w52 = (g < 3) ? __ldg(&W5[(k0 + 8) * 3 + g]) : 0.0f;
        float w53 = (g < 3) ? __ldg(&W5[(k1 + 8) * 3 + g]) : 0.0f;
        B5f[0] = h2u(w50, w51);
        B5f[1] = h2u(w52, w53);
        C5p = h2u((k0 < 3) ? __ldg(&b5[k0]) : 0.0f,
                  (k1 < 3) ? __ldg(&b5[k1]) : 0.0f);
    }

    const int warpbase = blockIdx.x * 1024 + w * 256;  // < 4M, int-safe
    if (warpbase >= n) return;

    // ---- prefetch state ----
    float cu, cv, cz;     // coords for iteration it
    float nu, nv, nz;     // coords for iteration it+1
    uint4 cr0, cr1;       // gather results for iteration it
    unsigned cwxy;        // packed (wx, wy) for iteration it

    auto load_coords = [&](int it, float& a, float& b, float& c) {
        int p = warpbase + it * 32 + lane;
        if (it < 8 && p < n) {
            const float* xp = x + p * 3;      // p*3 < 12M, int-safe
            a = __ldcs(xp + 0);
            b = __ldcs(xp + 1);
            c = __ldcs(xp + 2);
        } else {
            a = 0.0f; b = 0.0f; c = 0.0f;
        }
    };

    // prologue
    load_coords(0, cu, cv, cz);
    issue_gather(cu, cv, cr0, cr1, cwxy);
    load_coords(1, nu, nv, nz);

    for (int it = 0; it < 8; it++) {
        int pbase = warpbase + it * 32;
        if (pbase >= n) break;                 // warp-uniform

        // ---- fp16 bilinear lerp on prefetched data ----
        __half2 wxyh = u2h(cwxy);
        __half2 wx2  = __low2half2(wxyh);
        __half2 wy2  = __high2half2(wxyh);

        __half2 A01 = u2h(cr0.x), A23 = u2h(cr0.y);
        __half2 B01 = u2h(cr0.z), B23 = u2h(cr0.w);
        __half2 Cc01 = u2h(cr1.x), Cc23 = u2h(cr1.y);
        __half2 D01 = u2h(cr1.z), D23 = u2h(cr1.w);

        __half2 t01 = __hfma2(wx2, __hsub2(B01, A01), A01);
        __half2 t23 = __hfma2(wx2, __hsub2(B23, A23), A23);
        __half2 s01 = __hfma2(wx2, __hsub2(D01, Cc01), Cc01);
        __half2 s23 = __hfma2(wx2, __hsub2(D23, Cc23), Cc23);
        __half2 f01 = __hfma2(wy2, __hsub2(s01, t01), t01);
        __half2 f23 = __hfma2(wy2, __hsub2(s23, t23), t23);

        // ---- stage input row: [x,y,z,0,f0,f1,f2,f3] ----
        uint4 row;
        row.x = h2u(cu, cv);
        row.y = h2u(cz, 0.0f);
        row.z = *reinterpret_cast<unsigned*>(&f01);
        row.w = *reinterpret_cast<unsigned*>(&f23);
        sIn[w][lane] = row;
        __syncwarp();

        // ---- ldmatrix x4: two m16k8 A fragments ----
        unsigned a0, a1, a2, a3;
        unsigned addr = (unsigned)__cvta_generic_to_shared(&sIn[w][lane]);
        asm volatile(
            "ldmatrix.sync.aligned.m8n8.x4.shared.b16 {%0,%1,%2,%3}, [%4];\n"
            : "=r"(a0), "=r"(a1), "=r"(a2), "=r"(a3)
            : "r"(addr));
        __syncwarp();   // sIn reusable next iteration

        // ---- prefetch: gathers for it+1, coords for it+2 ----
        issue_gather(nu, nv, cr0, cr1, cwxy);
        cu = nu; cv = nv; cz = nz;
        load_coords(it + 2, nu, nv, nz);

        // ---- layer 1 (k=8) ----
        unsigned A[2][4];
        {
            float2 cb0 = __half22float2(u2h(C1p[0]));
            float2 cb1 = __half22float2(u2h(C1p[1]));
            unsigned A1[2][2] = {{a0, a1}, {a2, a3}};
#pragma unroll
            for (int T = 0; T < 2; T++) {
                float c0[4] = {cb0.x, cb0.y, cb0.x, cb0.y};
                float c1[4] = {cb1.x, cb1.y, cb1.x, cb1.y};
                float d0[4], d1[4];
                mma_1688(d0, A1[T], B1f[0], c0);
                mma_1688(d1, A1[T], B1f[1], c1);
                A[T][0] = relu_pack(d0[0], d0[1]);
                A[T][1] = relu_pack(d0[2], d0[3]);
                A[T][2] = relu_pack(d1[0], d1[1]);
                A[T][3] = relu_pack(d1[2], d1[3]);
            }
        }

        // ---- layers 2-4 ----
        hidden16(A, B2f, C2p);
        hidden16(A, B3f, C3p);
        hidden16(A, B4f, C4p);

        // ---- layer 5 (n=3 padded to 8, single n-tile) ----
        float d5[2][4];
        {
            float2 cb5 = __half22float2(u2h(C5p));
#pragma unroll
            for (int T = 0; T < 2; T++) {
                float c[4] = {cb5.x, cb5.y, cb5.x, cb5.y};
                mma_16816(d5[T], A[T], B5f, c);
            }
        }

        // ---- stage outputs ----
        if (q == 0) {
#pragma unroll
            for (int T = 0; T < 2; T++) {
                sOut[w][(T * 16 + g) * 3 + 0]     = d5[T][0];
                sOut[w][(T * 16 + g) * 3 + 1]     = d5[T][1];
                sOut[w][(T * 16 + g + 8) * 3 + 0] = d5[T][2];
                sOut[w][(T * 16 + g + 8) * 3 + 1] = d5[T][3];
            }
        } else if (q == 1) {
#pragma unroll
            for (int T = 0; T < 2; T++) {
                sOut[w][(T * 16 + g) * 3 + 2]     = d5[T][0];
                sOut[w][(T * 16 + g + 8) * 3 + 2] = d5[T][2];
            }
        }
        __syncwarp();

        // ---- store 96 contiguous floats (streaming) ----
        if (pbase + 32 <= n) {
            float4* dst = reinterpret_cast<float4*>(out + pbase * 3);
            const float4* src = reinterpret_cast<const float4*>(sOut[w]);
            if (lane < 24) __stcs(dst + lane, src[lane]);
        } else {
            int cnt = (n - pbase) * 3;
            for (int idx = lane; idx < cnt; idx += 32)
                out[pbase * 3 + idx] = sOut[w][idx];
        }
        __syncwarp();
    }
}

// ---------------------------------------------------------------------------
// kernel_launch — graph-capturable, allocation-free.
// ---------------------------------------------------------------------------
extern "C" void kernel_launch(void* const* d_in, const int* in_sizes, int n_in,
                              void* d_out, int out_size) {
    const float* x  = (const float*)d_in[0];
    const float* fm = (const float*)d_in[1];
    const float* W1 = (const float*)d_in[2];
    const float* b1 = (const float*)d_in[3];
    const float* W2 = (const float*)d_in[4];
    const float* b2 = (const float*)d_in[5];
    const float* W3 = (const float*)d_in[6];
    const float* b3 = (const float*)d_in[7];
    const float* W4 = (const float*)d_in[8];
    const float* b4 = (const float*)d_in[9];
    const float* W5 = (const float*)d_in[10];
    const float* b5 = (const float*)d_in[11];

    int n = in_sizes[0] / 3;   // 4,000,000 points

    fm_pack_kernel<<<(512 * 512 + 255) / 256, 256>>>(fm);

    int nblocks = (n + 1023) / 1024;   // 1024 points per block
    mlp_mma_kernel<<<nblocks, 128>>>(x, W1, b1, W2, b2, W3, b3, W4, b4, W5, b5,
                                     (float*)d_out, n);
}

// round 16
// speedup vs baseline: 1.1063x; 1.0085x over previous
#include <cuda_runtime.h>
#include <cuda_fp16.h>
#include <cstdint>

// ---------------------------------------------------------------------------
// Device scratch: featuremap as fp16, x-pair duplicated. Entry (y,x) is 16B:
//   [ c0..c3 @(y,x) , c0..c3 @(y,min(x+1,511)) ]  as 8 halves.
// One LDG.128 fetches BOTH x-taps of one row -> 2 loads per bilinear sample.
// ---------------------------------------------------------------------------
__device__ uint4 g_fmH[512 * 512];

__global__ void fm_pack_kernel(const float* __restrict__ fm) {
    int i = blockIdx.x * blockDim.x + threadIdx.x;
    if (i >= 512 * 512) return;
    int x  = i & 511;
    int xn = min(x + 1, 511);
    int j  = i - x + xn;

    __half2 p01 = __floats2half2_rn(fm[i],              fm[i + 262144]);
    __half2 p23 = __floats2half2_rn(fm[i + 2 * 262144], fm[i + 3 * 262144]);
    __half2 q01 = __floats2half2_rn(fm[j],              fm[j + 262144]);
    __half2 q23 = __floats2half2_rn(fm[j + 2 * 262144], fm[j + 3 * 262144]);

    uint4 e;
    e.x = *reinterpret_cast<unsigned*>(&p01);
    e.y = *reinterpret_cast<unsigned*>(&p23);
    e.z = *reinterpret_cast<unsigned*>(&q01);
    e.w = *reinterpret_cast<unsigned*>(&q23);
    g_fmH[i] = e;
}

// ---------------------------------------------------------------------------
// helpers
// ---------------------------------------------------------------------------
__device__ __forceinline__ unsigned h2u(float a, float b) {
    __half2 h = __floats2half2_rn(a, b);
    return *reinterpret_cast<unsigned*>(&h);
}
__device__ __forceinline__ unsigned relu_pack(float a, float b) {
    __half2 h = __floats2half2_rn(a, b);
    h = __hmax2(h, __floats2half2_rn(0.0f, 0.0f));
    return *reinterpret_cast<unsigned*>(&h);
}
__device__ __forceinline__ __half2 u2h(unsigned u) {
    return *reinterpret_cast<__half2*>(&u);
}

// m16n8k16 fp16 -> fp32
__device__ __forceinline__ void mma_16816(float d[4], const unsigned a[4],
                                          const unsigned b[2], const float c[4]) {
    asm volatile(
        "mma.sync.aligned.m16n8k16.row.col.f32.f16.f16.f32 "
        "{%0,%1,%2,%3}, {%4,%5,%6,%7}, {%8,%9}, {%10,%11,%12,%13};\n"
        : "=f"(d[0]), "=f"(d[1]), "=f"(d[2]), "=f"(d[3])
        : "r"(a[0]), "r"(a[1]), "r"(a[2]), "r"(a[3]),
          "r"(b[0]), "r"(b[1]),
          "f"(c[0]), "f"(c[1]), "f"(c[2]), "f"(c[3]));
}
// m16n8k8 fp16 -> fp32
__device__ __forceinline__ void mma_1688(float d[4], const unsigned a[2],
                                         unsigned b, const float c[4]) {
    asm volatile(
        "mma.sync.aligned.m16n8k8.row.col.f32.f16.f16.f32 "
        "{%0,%1,%2,%3}, {%4,%5}, {%6}, {%7,%8,%9,%10};\n"
        : "=f"(d[0]), "=f"(d[1]), "=f"(d[2]), "=f"(d[3])
        : "r"(a[0]), "r"(a[1]), "r"(b),
          "f"(c[0]), "f"(c[1]), "f"(c[2]), "f"(c[3]));
}

// hidden 16->16 layer on two m16 tiles; biases arrive packed as half2.
__device__ __forceinline__ void hidden16(unsigned A[2][4],
                                         const unsigned B[2][2],
                                         const unsigned Cp[2]) {
    float2 cb0 = __half22float2(u2h(Cp[0]));
    float2 cb1 = __half22float2(u2h(Cp[1]));
#pragma unroll
    for (int T = 0; T < 2; T++) {
        float c0[4] = {cb0.x, cb0.y, cb0.x, cb0.y};
        float c1[4] = {cb1.x, cb1.y, cb1.x, cb1.y};
        float d0[4], d1[4];
        mma_16816(d0, A[T], B[0], c0);
        mma_16816(d1, A[T], B[1], c1);
        A[T][0] = relu_pack(d0[0], d0[1]);
        A[T][1] = relu_pack(d0[2], d0[3]);
        A[T][2] = relu_pack(d1[0], d1[1]);
        A[T][3] = relu_pack(d1[2], d1[3]);
    }
}

// issue gather loads for one point; results + packed (wx,wy) carried in regs.
// address via exact fp32 fma: y0f*512 + x0f < 2^18, exact.
__device__ __forceinline__ void issue_gather(float u, float v,
                                             uint4& r0, uint4& r1,
                                             unsigned& wxy) {
    float fx = fminf(fmaxf(fmaf(u, 512.0f, -0.5f), 0.0f), 511.0f);
    float fy = fminf(fmaxf(fmaf(v, 512.0f, -0.5f), 0.0f), 511.0f);
    float x0f = floorf(fx), y0f = floorf(fy);
    wxy = h2u(fx - x0f, fy - y0f);
    int idx0 = (int)fmaf(y0f, 512.0f, x0f);
    int idx1 = (int)fmaf(fminf(y0f + 1.0f, 511.0f), 512.0f, x0f);
    r0 = __ldg(&g_fmH[idx0]);
    r1 = __ldg(&g_fmH[idx1]);
}

// ---------------------------------------------------------------------------
// Main kernel: 4 warps/block, each warp 8 iterations x 32 points = 256 pts.
// Coords prefetched 2 iterations ahead, gathers 1 iteration ahead.
// sIn/sOut double-buffered (1 syncwarp per iteration). 7 blocks/SM target.
// ---------------------------------------------------------------------------
__global__ __launch_bounds__(128, 7) void mlp_mma_kernel(
    const float* __restrict__ x,
    const float* __restrict__ W1, const float* __restrict__ b1,
    const float* __restrict__ W2, const float* __restrict__ b2,
    const float* __restrict__ W3, const float* __restrict__ b3,
    const float* __restrict__ W4, const float* __restrict__ b4,
    const float* __restrict__ W5, const float* __restrict__ b5,
    float* __restrict__ out, int n)
{
    __shared__ uint4 sIn[2][4][32];    // [buf][warp][row], 4 KB
    __shared__ float sOut[2][4][96];   // [buf][warp][...], 3 KB

    const int tid  = threadIdx.x;
    const int w    = tid >> 5;
    const int lane = tid & 31;
    const int g    = lane >> 2;       // 0..7
    const int q    = lane & 3;        // 0..3
    const int k0   = 2 * q;
    const int k1   = 2 * q + 1;

    // ---- per-thread weight/bias fragments (loaded once) ----
    // input row layout: [x, y, z, 0, f0, f1, f2, f3]  (pad at k=3)
    unsigned B1f[2];        unsigned C1p[2];
    unsigned B2f[2][2];     unsigned C2p[2];
    unsigned B3f[2][2];     unsigned C3p[2];
    unsigned B4f[2][2];     unsigned C4p[2];
    unsigned B5f[2];        unsigned C5p;

#pragma unroll
    for (int t = 0; t < 2; t++) {
        int nn = 8 * t + g;
        float w0 = (k0 < 3) ? __ldg(&W1[k0 * 16 + nn])
                            : ((k0 == 3) ? 0.0f : __ldg(&W1[(k0 - 1) * 16 + nn]));
        float w1 = (k1 < 3) ? __ldg(&W1[k1 * 16 + nn])
                            : ((k1 == 3) ? 0.0f : __ldg(&W1[(k1 - 1) * 16 + nn]));
        B1f[t] = h2u(w0, w1);
        C1p[t] = h2u(__ldg(&b1[8 * t + k0]), __ldg(&b1[8 * t + k1]));

        B2f[t][0] = h2u(__ldg(&W2[k0 * 16 + nn]),       __ldg(&W2[k1 * 16 + nn]));
        B2f[t][1] = h2u(__ldg(&W2[(k0 + 8) * 16 + nn]), __ldg(&W2[(k1 + 8) * 16 + nn]));
        C2p[t] = h2u(__ldg(&b2[8 * t + k0]), __ldg(&b2[8 * t + k1]));

        B3f[t][0] = h2u(__ldg(&W3[k0 * 16 + nn]),       __ldg(&W3[k1 * 16 + nn]));
        B3f[t][1] = h2u(__ldg(&W3[(k0 + 8) * 16 + nn]), __ldg(&W3[(k1 + 8) * 16 + nn]));
        C3p[t] = h2u(__ldg(&b3[8 * t + k0]), __ldg(&b3[8 * t + k1]));

        B4f[t][0] = h2u(__ldg(&W4[k0 * 16 + nn]),       __ldg(&W4[k1 * 16 + nn]));
        B4f[t][1] = h2u(__ldg(&W4[(k0 + 8) * 16 + nn]), __ldg(&W4[(k1 + 8) * 16 + nn]));
        C4p[t] = h2u(__ldg(&b4[8 * t + k0]), __ldg(&b4[8 * t + k1]));
    }
    {
        float w50 = (g < 3) ? __ldg(&W5[k0 * 3 + g]) : 0.0f;
        float w51 = (g < 3) ? __ldg(&W5[k1 * 3 + g]) : 0.0f;
        float w52 = (g < 3) ? __ldg(&W5[(k0 + 8) * 3 + g]) : 0.0f;
        float w53 = (g < 3) ? __ldg(&W5[(k1 + 8) * 3 + g]) : 0.0f;
        B5f[0] = h2u(w50, w51);
        B5f[1] = h2u(w52, w53);
        C5p = h2u((k0 < 3) ? __ldg(&b5[k0]) : 0.0f,
                  (k1 < 3) ? __ldg(&b5[k1]) : 0.0f);
    }

    const int warpbase = blockIdx.x * 1024 + w * 256;  // < 4M, int-safe
    if (warpbase >= n) return;

    // ---- prefetch state ----
    float cu, cv, cz;     // coords for iteration it
    float nu, nv, nz;     // coords for iteration it+1
    uint4 cr0, cr1;       // gather results for iteration it
    unsigned cwxy;        // packed (wx, wy) for iteration it

    auto load_coords = [&](int it, float& a, float& b, float& c) {
        int p = warpbase + it * 32 + lane;
        if (it < 8 && p < n) {
            const float* xp = x + p * 3;      // p*3 < 12M, int-safe
            a = __ldcs(xp + 0);
            b = __ldcs(xp + 1);
            c = __ldcs(xp + 2);
        } else {
            a = 0.0f; b = 0.0f; c = 0.0f;
        }
    };

    // prologue
    load_coords(0, cu, cv, cz);
    issue_gather(cu, cv, cr0, cr1, cwxy);
    load_coords(1, nu, nv, nz);

    for (int it = 0; it < 8; it++) {
        int pbase = warpbase + it * 32;
        if (pbase >= n) break;                 // warp-uniform
        const int buf = it & 1;

        // ---- fp16 bilinear lerp on prefetched data ----
        __half2 wxyh = u2h(cwxy);
        __half2 wx2  = __low2half2(wxyh);
        __half2 wy2  = __high2half2(wxyh);

        __half2 A01 = u2h(cr0.x), A23 = u2h(cr0.y);
        __half2 B01 = u2h(cr0.z), B23 = u2h(cr0.w);
        __half2 Cc01 = u2h(cr1.x), Cc23 = u2h(cr1.y);
        __half2 D01 = u2h(cr1.z), D23 = u2h(cr1.w);

        __half2 t01 = __hfma2(wx2, __hsub2(B01, A01), A01);
        __half2 t23 = __hfma2(wx2, __hsub2(B23, A23), A23);
        __half2 s01 = __hfma2(wx2, __hsub2(D01, Cc01), Cc01);
        __half2 s23 = __hfma2(wx2, __hsub2(D23, Cc23), Cc23);
        __half2 f01 = __hfma2(wy2, __hsub2(s01, t01), t01);
        __half2 f23 = __hfma2(wy2, __hsub2(s23, t23), t23);

        // ---- stage input row: [x,y,z,0,f0,f1,f2,f3] ----
        uint4 row;
        row.x = h2u(cu, cv);
        row.y = h2u(cz, 0.0f);
        row.z = *reinterpret_cast<unsigned*>(&f01);
        row.w = *reinterpret_cast<unsigned*>(&f23);
        sIn[buf][w][lane] = row;
        __syncwarp();

        // ---- ldmatrix x4: two m16k8 A fragments ----
        unsigned a0, a1, a2, a3;
        unsigned addr = (unsigned)__cvta_generic_to_shared(&sIn[buf][w][lane]);
        asm volatile(
            "ldmatrix.sync.aligned.m8n8.x4.shared.b16 {%0,%1,%2,%3}, [%4];\n"
            : "=r"(a0), "=r"(a1), "=r"(a2), "=r"(a3)
            : "r"(addr));

        // ---- prefetch: gathers for it+1, coords for it+2 ----
        issue_gather(nu, nv, cr0, cr1, cwxy);
        cu = nu; cv = nv; cz = nz;
        load_coords(it + 2, nu, nv, nz);

        // ---- layer 1 (k=8) ----
        unsigned A[2][4];
        {
            float2 cb0 = __half22float2(u2h(C1p[0]));
            float2 cb1 = __half22float2(u2h(C1p[1]));
            unsigned A1[2][2] = {{a0, a1}, {a2, a3}};
#pragma unroll
            for (int T = 0; T < 2; T++) {
                float c0[4] = {cb0.x, cb0.y, cb0.x, cb0.y};
                float c1[4] = {cb1.x, cb1.y, cb1.x, cb1.y};
                float d0[4], d1[4];
                mma_1688(d0, A1[T], B1f[0], c0);
                mma_1688(d1, A1[T], B1f[1], c1);
                A[T][0] = relu_pack(d0[0], d0[1]);
                A[T][1] = relu_pack(d0[2], d0[3]);
                A[T][2] = relu_pack(d1[0], d1[1]);
                A[T][3] = relu_pack(d1[2], d1[3]);
            }
        }

        // ---- layers 2-4 ----
        hidden16(A, B2f, C2p);
        hidden16(A, B3f, C3p);
        hidden16(A, B4f, C4p);

        // ---- layer 5 (n=3 padded to 8, single n-tile) ----
        float d5[2][4];
        {
            float2 cb5 = __half22float2(u2h(C5p));
#pragma unroll
            for (int T = 0; T < 2; T++) {
                float c[4] = {cb5.x, cb5.y, cb5.x, cb5.y};
                mma_16816(d5[T], A[T], B5f, c);
            }
        }

        // ---- stage outputs (double-buffered; only 1 syncwarp per iter) ----
        if (q == 0) {
#pragma unroll
            for (int T = 0; T < 2; T++) {
                sOut[buf][w][(T * 16 + g) * 3 + 0]     = d5[T][0];
                sOut[buf][w][(T * 16 + g) * 3 + 1]     = d5[T][1];
                sOut[buf][w][(T * 16 + g + 8) * 3 + 0] = d5[T][2];
                sOut[buf][w][(T * 16 + g + 8) * 3 + 1] = d5[T][3];
            }
        } else if (q == 1) {
#pragma unroll
            for (int T = 0; T < 2; T++) {
                sOut[buf][w][(T * 16 + g) * 3 + 2]     = d5[T][0];
                sOut[buf][w][(T * 16 + g + 8) * 3 + 2] = d5[T][2];
            }
        }
        __syncwarp();

        // ---- store 96 contiguous floats (streaming) ----
        if (pbase + 32 <= n) {
            float4* dst = reinterpret_cast<float4*>(out + pbase * 3);
            const float4* src = reinterpret_cast<const float4*>(sOut[buf][w]);
            if (lane < 24) __stcs(dst + lane, src[lane]);
        } else {
            int cnt = (n - pbase) * 3;
            for (int idx = lane; idx < cnt; idx += 32)
                out[pbase * 3 + idx] = sOut[buf][w][idx];
        }
        // no trailing syncwarp: next iteration uses the other buffer
    }
}

// ---------------------------------------------------------------------------
// kernel_launch — graph-capturable, allocation-free.
// ---------------------------------------------------------------------------
extern "C" void kernel_launch(void* const* d_in, const int* in_sizes, int n_in,
                              void* d_out, int out_size) {
    const float* x  = (const float*)d_in[0];
    const float* fm = (const float*)d_in[1];
    const float* W1 = (const float*)d_in[2];
    const float* b1 = (const float*)d_in[3];
    const float* W2 = (const float*)d_in[4];
    const float* b2 = (const float*)d_in[5];
    const float* W3 = (const float*)d_in[6];
    const float* b3 = (const float*)d_in[7];
    const float* W4 = (const float*)d_in[8];
    const float* b4 = (const float*)d_in[9];
    const float* W5 = (const float*)d_in[10];
    const float* b5 = (const float*)d_in[11];

    int n = in_sizes[0] / 3;   // 4,000,000 points

    fm_pack_kernel<<<(512 * 512 + 255) / 256, 256>>>(fm);

    int nblocks = (n + 1023) / 1024;   // 1024 points per block
    mlp_mma_kernel<<<nblocks, 128>>>(x, W1, b1, W2, b2, W3, b3, W4, b4, W5, b5,
                                     (float*)d_out, n);
}